// round 14
// baseline (speedup 1.0000x reference)
#include <cuda_runtime.h>

// NonMaxSuppression: 3x3 local max + thr 0.6 + 10px border on (16,1,1536,1536) f32.
// Output: float32 [2, K]; row 0 = y, row 1 = x, in row-major (b,y,x) nonzero order.
//
//   countk : 32-row strips; 12 warps = 6 x 256-px segments x 2 row-halves.
//            8 px/thread (2 float4), rolling registers; shfl neighbor exchange;
//            2-level xor pack (byte->word); in-kernel per-row counts via popc
//            xor-reduce + one smem reduce. Border x masked in words 0/47.
//   scank  : chunked register scan (24 rows/thread) + warp-shuffle block scan.
//   emitk  : warp per row; decode mask bits into smem x-list, then fully
//            coalesced ordered stores. No atomics; fully deterministic.

#define Bn 16
#define Hn 1536
#define Wn 1536
#define W4 (Wn / 4)                 // 384 float4 per row
#define WPR 48                      // 32-px words per row
#define HIN (Hn - 20)               // 1516 interior rows per image
#define NRI (Bn * HIN)              // 24256 interior rows total
#define ROWS 32                     // rows per countk strip
#define SPI ((HIN + ROWS - 1) / ROWS)   // 48 strips per image
#define RPT 24                      // rows per scan thread

__device__ unsigned g_mask[(size_t)NRI * WPR];   // 4.7 MB candidate bitmask
__device__ int g_rowcnt[NRI];
__device__ int g_rowoff[NRI];

__device__ __forceinline__ float fmax3(float a, float b, float c) {
    return fmaxf(a, fmaxf(b, c));
}

__global__ __launch_bounds__(384) void countk(const float* __restrict__ rep) {
    const int blk = blockIdx.x;
    const int b   = blk / SPI;
    const int s   = blk % SPI;
    const int y0  = 10 + s * ROWS;
    const int nrows = min(ROWS, (Hn - 10) - y0);
    const int tid  = threadIdx.x;
    const int lane = tid & 31;
    const int wid  = tid >> 5;
    const int g    = wid / 6;                 // row-half 0/1
    const int seg  = wid % 6;                 // 256-px column segment
    const int nr   = min(16, nrows - g * 16); // rows for this warp
    const int ys   = y0 + g * 16;
    const int x0   = seg * 256 + lane * 8;
    const int t4   = x0 >> 2;                 // first float4 index

    const float* img = rep + (size_t)b * Hn * Wn;
    const float4* col = (const float4*)img;

    // halo column: lane 0 -> x0-1, lane 31 -> x0+8 (clamped; clamped bits border-masked)
    const bool isEdge = (lane == 0) | (lane == 31);
    const int hx = (lane == 0) ? max(x0 - 1, 0) : min(x0 + 8, Wn - 1);

    __shared__ int scnt[12][16];

    if (nr > 0) {
        float4 rpA = col[(size_t)(ys - 1) * W4 + t4];
        float4 rpB = col[(size_t)(ys - 1) * W4 + t4 + 1];
        float4 rcA = col[(size_t)ys       * W4 + t4];
        float4 rcB = col[(size_t)ys       * W4 + t4 + 1];
        float hp = isEdge ? img[(size_t)(ys - 1) * Wn + hx] : 0.0f;
        float hc = isEdge ? img[(size_t)ys       * Wn + hx] : 0.0f;

        const int ridBase = b * HIN + (y0 - 10) + g * 16;
        const int gw = seg * 8 + (lane >> 2);     // global word index 0..47
        const bool leader = (lane & 3) == 0;

        #pragma unroll 4
        for (int i = 0; i < nr; ++i) {
            const int y = ys + i;
            const float4 rnA = col[(size_t)(y + 1) * W4 + t4];
            const float4 rnB = col[(size_t)(y + 1) * W4 + t4 + 1];
            const float hn = isEdge ? img[(size_t)(y + 1) * Wn + hx] : 0.0f;

            float4 vA, vB;                        // vertical 3-max, 8 px
            vA.x = fmax3(rpA.x, rcA.x, rnA.x);
            vA.y = fmax3(rpA.y, rcA.y, rnA.y);
            vA.z = fmax3(rpA.z, rcA.z, rnA.z);
            vA.w = fmax3(rpA.w, rcA.w, rnA.w);
            vB.x = fmax3(rpB.x, rcB.x, rnB.x);
            vB.y = fmax3(rpB.y, rcB.y, rnB.y);
            vB.z = fmax3(rpB.z, rcB.z, rnB.z);
            vB.w = fmax3(rpB.w, rcB.w, rnB.w);
            const float hv = fmax3(hp, hc, hn);

            float left  = __shfl_up_sync(0xffffffffu, vB.w, 1);
            float right = __shfl_down_sync(0xffffffffu, vA.x, 1);
            if (lane == 0)  left  = hv;
            if (lane == 31) right = hv;

            // candidate: center >= thr and >= 3x3 max (v* includes center)
            const bool c0 = rcA.x >= 0.6f && rcA.x >= left && rcA.x >= vA.x && rcA.x >= vA.y;
            const bool c1 = rcA.y >= 0.6f && rcA.y >= vA.x && rcA.y >= vA.y && rcA.y >= vA.z;
            const bool c2 = rcA.z >= 0.6f && rcA.z >= vA.y && rcA.z >= vA.z && rcA.z >= vA.w;
            const bool c3 = rcA.w >= 0.6f && rcA.w >= vA.z && rcA.w >= vA.w && rcA.w >= vB.x;
            const bool c4 = rcB.x >= 0.6f && rcB.x >= vA.w && rcB.x >= vB.x && rcB.x >= vB.y;
            const bool c5 = rcB.y >= 0.6f && rcB.y >= vB.x && rcB.y >= vB.y && rcB.y >= vB.z;
            const bool c6 = rcB.z >= 0.6f && rcB.z >= vB.y && rcB.z >= vB.z && rcB.z >= vB.w;
            const bool c7 = rcB.w >= 0.6f && rcB.w >= vB.z && rcB.w >= vB.w && rcB.w >= right;
            const unsigned nib =  (unsigned)c0        | ((unsigned)c1 << 1)
                               | ((unsigned)c2 << 2) | ((unsigned)c3 << 3)
                               | ((unsigned)c4 << 4) | ((unsigned)c5 << 5)
                               | ((unsigned)c6 << 6) | ((unsigned)c7 << 7);

            // pack 4 lanes x 8 bits -> word; all 4 lanes of a group end with it
            unsigned v = nib << (8 * (lane & 3));
            v |= __shfl_xor_sync(0xffffffffu, v, 1);
            v |= __shfl_xor_sync(0xffffffffu, v, 2);
            if (gw == 0)       v &= ~0x3FFu;          // x < 10
            if (gw == WPR - 1) v &= 0x003FFFFFu;      // x >= 1526
            if (leader)
                g_mask[(size_t)(ridBase + i) * WPR + gw] = v;

            // row count for this warp's 256 px: sum popc over the 8 groups
            int c = __popc(v);
            c += __shfl_xor_sync(0xffffffffu, c, 4);
            c += __shfl_xor_sync(0xffffffffu, c, 8);
            c += __shfl_xor_sync(0xffffffffu, c, 16);
            if (lane == 0) scnt[wid][i] = c;

            rpA = rcA; rpB = rcB; rcA = rnA; rcB = rnB; hp = hc; hc = hn;
        }
    }
    __syncthreads();
    if (tid < ROWS && tid < nrows) {                  // sum 6 segment warps per row
        const int gg = tid >> 4, li = tid & 15;
        int ssum = 0;
        #pragma unroll
        for (int w = 0; w < 6; ++w) ssum += scnt[gg * 6 + w][li];
        g_rowcnt[b * HIN + (y0 - 10) + tid] = ssum;
    }
}

__global__ __launch_bounds__(1024) void scank() {
    const int tid  = threadIdx.x;
    const int lane = tid & 31;
    const int wid  = tid >> 5;
    int loc[RPT];
    int s = 0;
    #pragma unroll
    for (int i = 0; i < RPT; ++i) {
        const int idx = tid * RPT + i;
        loc[i] = s;
        s += (idx < NRI) ? g_rowcnt[idx] : 0;
    }
    int v = s;
    #pragma unroll
    for (int o = 1; o < 32; o <<= 1) {
        const int u = __shfl_up_sync(0xffffffffu, v, o);
        if (lane >= o) v += u;
    }
    __shared__ int ws[32];
    if (lane == 31) ws[wid] = v;
    __syncthreads();
    if (wid == 0) {
        int w = ws[lane];
        #pragma unroll
        for (int o = 1; o < 32; o <<= 1) {
            const int u = __shfl_up_sync(0xffffffffu, w, o);
            if (lane >= o) w += u;
        }
        ws[lane] = w;
    }
    __syncthreads();
    const int excl = (v - s) + (wid > 0 ? ws[wid - 1] : 0);
    #pragma unroll
    for (int i = 0; i < RPT; ++i) {
        const int idx = tid * RPT + i;
        if (idx < NRI) g_rowoff[idx] = excl + loc[i];
    }
}

__global__ __launch_bounds__(256) void emitk(float* __restrict__ out, int K) {
    __shared__ unsigned short sx[8][Wn];              // 24 KB: x-coords per row
    const int tid  = threadIdx.x;
    const int lane = tid & 31;
    const int wid  = tid >> 5;
    const int r    = blockIdx.x * 8 + wid;
    const int y    = 10 + r % HIN;
    const unsigned* mrow = g_mask + (size_t)r * WPR;
    const int off = g_rowoff[r];

    const unsigned wA = mrow[lane];
    const unsigned wB = (lane < WPR - 32) ? mrow[32 + lane] : 0u;
    const int pcA = __popc(wA);
    const int pcB = __popc(wB);

    int scA = pcA, scB = pcB;                         // inclusive warp scans
    #pragma unroll
    for (int o = 1; o < 32; o <<= 1) {
        const int uA = __shfl_up_sync(0xffffffffu, scA, o);
        const int uB = __shfl_up_sync(0xffffffffu, scB, o);
        if (lane >= o) { scA += uA; scB += uB; }
    }
    const int totalA = __shfl_sync(0xffffffffu, scA, 31);
    const int cnt    = totalA + __shfl_sync(0xffffffffu, scB, 31);

    // decode bits into smem x-list at ordered local offsets
    int j = scA - pcA;
    unsigned w = wA;
    int xb = lane * 32;
    while (w) {
        const int bit = __ffs(w) - 1;
        w &= w - 1;
        sx[wid][j++] = (unsigned short)(xb + bit);
    }
    j = totalA + scB - pcB;
    w = wB;
    xb = (32 + lane) * 32;
    while (w) {
        const int bit = __ffs(w) - 1;
        w &= w - 1;
        sx[wid][j++] = (unsigned short)(xb + bit);
    }
    __syncwarp();

    const float fy = (float)y;
    const int lim = min(cnt, K - off);                // defensive bound
    for (int i = lane; i < lim; i += 32) {
        out[off + i]     = fy;
        out[K + off + i] = (float)sx[wid][i];
    }
}

extern "C" void kernel_launch(void* const* d_in, const int* in_sizes, int n_in,
                              void* d_out, int out_size) {
    const float* rep = (const float*)d_in[0];
    float* out = (float*)d_out;
    const int K = out_size / 2;
    countk<<<Bn * SPI, 384>>>(rep);
    scank<<<1, 1024>>>();
    emitk<<<NRI / 8, 256>>>(out, K);
}

// round 15
// speedup vs baseline: 1.0806x; 1.0806x over previous
#include <cuda_runtime.h>

// NonMaxSuppression: 3x3 local max + thr 0.6 + 10px border on (16,1,1536,1536) f32.
// Output: float32 [2, K]; row 0 = y, row 1 = x, in row-major (b,y,x) nonzero order.
//
//   countk  : 32-row strips; 12 warps = 6 x 256-px segments x 2 row-halves.
//             8 px/thread (2 float4), rolling registers; 1 shfl-pair neighbor
//             exchange + 1 shfl pack -> ushort stores. No counts, no smem.
//   rowcntk : warp per row popc over mask words -> g_rowcnt (L2-resident).
//   scank   : chunked register scan (24 rows/thread) + warp-shuffle block scan.
//   emitk   : warp per row; decode mask bits into smem x-list, then fully
//             coalesced ordered stores. No atomics; fully deterministic.

#define Bn 16
#define Hn 1536
#define Wn 1536
#define W4 (Wn / 4)                 // 384 float4 per row
#define WPR 48                      // 32-px words per row
#define HIN (Hn - 20)               // 1516 interior rows per image
#define NRI (Bn * HIN)              // 24256 interior rows total
#define ROWS 32                     // rows per countk strip
#define SPI ((HIN + ROWS - 1) / ROWS)   // 48 strips per image
#define RPT 24                      // rows per scan thread

__device__ unsigned g_mask[(size_t)NRI * WPR];   // 4.7 MB candidate bitmask
__device__ int g_rowcnt[NRI];
__device__ int g_rowoff[NRI];

__device__ __forceinline__ float fmax3(float a, float b, float c) {
    return fmaxf(a, fmaxf(b, c));
}

__global__ __launch_bounds__(384, 3) void countk(const float* __restrict__ rep) {
    const int blk = blockIdx.x;
    const int b   = blk / SPI;
    const int s   = blk % SPI;
    const int y0  = 10 + s * ROWS;
    const int nrows = min(ROWS, (Hn - 10) - y0);
    const int tid  = threadIdx.x;
    const int lane = tid & 31;
    const int wid  = tid >> 5;
    const int g    = wid / 6;                 // row-half 0/1
    const int seg  = wid % 6;                 // 256-px column segment
    const int nr   = min(16, nrows - g * 16); // rows for this warp
    if (nr <= 0) return;
    const int ys   = y0 + g * 16;
    const int x0   = seg * 256 + lane * 8;
    const int t4   = x0 >> 2;                 // first float4 index

    const float* img = rep + (size_t)b * Hn * Wn;
    const float4* col = (const float4*)img;

    // halo column: lane 0 -> x0-1, lane 31 -> x0+8 (clamped; clamped bits border-masked)
    const bool isEdge = (lane == 0) | (lane == 31);
    const int hx = (lane == 0) ? max(x0 - 1, 0) : min(x0 + 8, Wn - 1);

    float4 rpA = col[(size_t)(ys - 1) * W4 + t4];
    float4 rpB = col[(size_t)(ys - 1) * W4 + t4 + 1];
    float4 rcA = col[(size_t)ys       * W4 + t4];
    float4 rcB = col[(size_t)ys       * W4 + t4 + 1];
    float hp = isEdge ? img[(size_t)(ys - 1) * Wn + hx] : 0.0f;
    float hc = isEdge ? img[(size_t)ys       * Wn + hx] : 0.0f;

    const int ridBase = b * HIN + (y0 - 10) + g * 16;
    const int gw = seg * 8 + (lane >> 2);         // global 32-bit word index 0..47
    // ushort store slot: even lanes store one 16-bit half each
    const bool leader = (lane & 1) == 0;
    const int uidx = gw * 2 + ((lane & 3) >> 1);  // ushort index within row
    unsigned short* gm16 = (unsigned short*)g_mask;

    #pragma unroll 4
    for (int i = 0; i < nr; ++i) {
        const int y = ys + i;
        const float4 rnA = col[(size_t)(y + 1) * W4 + t4];
        const float4 rnB = col[(size_t)(y + 1) * W4 + t4 + 1];
        const float hn = isEdge ? img[(size_t)(y + 1) * Wn + hx] : 0.0f;

        float4 vA, vB;                            // vertical 3-max, 8 px
        vA.x = fmax3(rpA.x, rcA.x, rnA.x);
        vA.y = fmax3(rpA.y, rcA.y, rnA.y);
        vA.z = fmax3(rpA.z, rcA.z, rnA.z);
        vA.w = fmax3(rpA.w, rcA.w, rnA.w);
        vB.x = fmax3(rpB.x, rcB.x, rnB.x);
        vB.y = fmax3(rpB.y, rcB.y, rnB.y);
        vB.z = fmax3(rpB.z, rcB.z, rnB.z);
        vB.w = fmax3(rpB.w, rcB.w, rnB.w);
        const float hv = fmax3(hp, hc, hn);

        float left  = __shfl_up_sync(0xffffffffu, vB.w, 1);
        float right = __shfl_down_sync(0xffffffffu, vA.x, 1);
        if (lane == 0)  left  = hv;
        if (lane == 31) right = hv;

        // candidate: center >= thr and >= 3x3 max (v* includes center)
        const bool c0 = rcA.x >= 0.6f && rcA.x >= left && rcA.x >= vA.x && rcA.x >= vA.y;
        const bool c1 = rcA.y >= 0.6f && rcA.y >= vA.x && rcA.y >= vA.y && rcA.y >= vA.z;
        const bool c2 = rcA.z >= 0.6f && rcA.z >= vA.y && rcA.z >= vA.z && rcA.z >= vA.w;
        const bool c3 = rcA.w >= 0.6f && rcA.w >= vA.z && rcA.w >= vA.w && rcA.w >= vB.x;
        const bool c4 = rcB.x >= 0.6f && rcB.x >= vA.w && rcB.x >= vB.x && rcB.x >= vB.y;
        const bool c5 = rcB.y >= 0.6f && rcB.y >= vB.x && rcB.y >= vB.y && rcB.y >= vB.z;
        const bool c6 = rcB.z >= 0.6f && rcB.z >= vB.y && rcB.z >= vB.z && rcB.z >= vB.w;
        const bool c7 = rcB.w >= 0.6f && rcB.w >= vB.z && rcB.w >= vB.w && rcB.w >= right;
        const unsigned nib =  (unsigned)c0        | ((unsigned)c1 << 1)
                           | ((unsigned)c2 << 2) | ((unsigned)c3 << 3)
                           | ((unsigned)c4 << 4) | ((unsigned)c5 << 5)
                           | ((unsigned)c6 << 6) | ((unsigned)c7 << 7);

        // pack lane pairs: one xor-shfl -> each pair holds a valid 16-bit half
        unsigned v = nib << (8 * (lane & 3));
        v |= __shfl_xor_sync(0xffffffffu, v, 1);
        if (gw == 0)       v &= ~0x3FFu;          // x < 10
        if (gw == WPR - 1) v &= 0x003FFFFFu;      // x >= 1526
        if (leader) {
            const unsigned short h =
                (unsigned short)((lane & 2) ? (v >> 16) : (v & 0xFFFFu));
            gm16[(size_t)(ridBase + i) * (WPR * 2) + uidx] = h;
        }

        rpA = rcA; rpB = rcB; rcA = rnA; rcB = rnB; hp = hc; hc = hn;
    }
}

__global__ __launch_bounds__(256) void rowcntk() {
    const int tid  = threadIdx.x;
    const int lane = tid & 31;
    const int r    = blockIdx.x * 8 + (tid >> 5);
    const unsigned* mrow = g_mask + (size_t)r * WPR;
    int c = __popc(mrow[lane]) + ((lane < WPR - 32) ? __popc(mrow[32 + lane]) : 0);
    #pragma unroll
    for (int o = 16; o > 0; o >>= 1)
        c += __shfl_down_sync(0xffffffffu, c, o);
    if (lane == 0) g_rowcnt[r] = c;
}

__global__ __launch_bounds__(1024) void scank() {
    const int tid  = threadIdx.x;
    const int lane = tid & 31;
    const int wid  = tid >> 5;
    int loc[RPT];
    int s = 0;
    #pragma unroll
    for (int i = 0; i < RPT; ++i) {
        const int idx = tid * RPT + i;
        loc[i] = s;
        s += (idx < NRI) ? g_rowcnt[idx] : 0;
    }
    int v = s;
    #pragma unroll
    for (int o = 1; o < 32; o <<= 1) {
        const int u = __shfl_up_sync(0xffffffffu, v, o);
        if (lane >= o) v += u;
    }
    __shared__ int ws[32];
    if (lane == 31) ws[wid] = v;
    __syncthreads();
    if (wid == 0) {
        int w = ws[lane];
        #pragma unroll
        for (int o = 1; o < 32; o <<= 1) {
            const int u = __shfl_up_sync(0xffffffffu, w, o);
            if (lane >= o) w += u;
        }
        ws[lane] = w;
    }
    __syncthreads();
    const int excl = (v - s) + (wid > 0 ? ws[wid - 1] : 0);
    #pragma unroll
    for (int i = 0; i < RPT; ++i) {
        const int idx = tid * RPT + i;
        if (idx < NRI) g_rowoff[idx] = excl + loc[i];
    }
}

__global__ __launch_bounds__(256) void emitk(float* __restrict__ out, int K) {
    __shared__ unsigned short sx[8][Wn];              // 24 KB: x-coords per row
    const int tid  = threadIdx.x;
    const int lane = tid & 31;
    const int wid  = tid >> 5;
    const int r    = blockIdx.x * 8 + wid;
    const int y    = 10 + r % HIN;
    const unsigned* mrow = g_mask + (size_t)r * WPR;
    const int off = g_rowoff[r];

    const unsigned wA = mrow[lane];
    const unsigned wB = (lane < WPR - 32) ? mrow[32 + lane] : 0u;
    const int pcA = __popc(wA);
    const int pcB = __popc(wB);

    int scA = pcA, scB = pcB;                         // inclusive warp scans
    #pragma unroll
    for (int o = 1; o < 32; o <<= 1) {
        const int uA = __shfl_up_sync(0xffffffffu, scA, o);
        const int uB = __shfl_up_sync(0xffffffffu, scB, o);
        if (lane >= o) { scA += uA; scB += uB; }
    }
    const int totalA = __shfl_sync(0xffffffffu, scA, 31);
    const int cnt    = totalA + __shfl_sync(0xffffffffu, scB, 31);

    // decode bits into smem x-list at ordered local offsets
    int j = scA - pcA;
    unsigned w = wA;
    int xb = lane * 32;
    while (w) {
        const int bit = __ffs(w) - 1;
        w &= w - 1;
        sx[wid][j++] = (unsigned short)(xb + bit);
    }
    j = totalA + scB - pcB;
    w = wB;
    xb = (32 + lane) * 32;
    while (w) {
        const int bit = __ffs(w) - 1;
        w &= w - 1;
        sx[wid][j++] = (unsigned short)(xb + bit);
    }
    __syncwarp();

    const float fy = (float)y;
    const int lim = min(cnt, K - off);                // defensive bound
    for (int i = lane; i < lim; i += 32) {
        out[off + i]     = fy;
        out[K + off + i] = (float)sx[wid][i];
    }
}

extern "C" void kernel_launch(void* const* d_in, const int* in_sizes, int n_in,
                              void* d_out, int out_size) {
    const float* rep = (const float*)d_in[0];
    float* out = (float*)d_out;
    const int K = out_size / 2;
    countk<<<Bn * SPI, 384>>>(rep);
    rowcntk<<<NRI / 8, 256>>>();
    scank<<<1, 1024>>>();
    emitk<<<NRI / 8, 256>>>(out, K);
}

// round 16
// speedup vs baseline: 1.1432x; 1.0579x over previous
#include <cuda_runtime.h>

// NonMaxSuppression: 3x3 local max + thr 0.6 + 10px border on (16,1,1536,1536) f32.
// Output: float32 [2, K]; row 0 = y, row 1 = x, in row-major (b,y,x) nonzero order.
//
//   countk  : 32-row strips; 12 warps = 6 x 256-px segments x 2 row-halves.
//             8 px/thread (2 float4), rolling registers. Candidate test folded
//             into ONE compare per px: mid >= fmax(vl, v, vr, THR) (max-algebra
//             conjunction fold -> no FSETP.AND chains). 1 shfl pack -> ushort.
//   rowcntk : warp per row popc over mask words -> g_rowcnt (L2-resident).
//   scank   : chunked register scan (24 rows/thread) + warp-shuffle block scan.
//   emitk   : warp per row; decode mask bits into smem x-list, then fully
//             coalesced ordered stores. No atomics; fully deterministic.

#define Bn 16
#define Hn 1536
#define Wn 1536
#define W4 (Wn / 4)                 // 384 float4 per row
#define WPR 48                      // 32-px words per row
#define HIN (Hn - 20)               // 1516 interior rows per image
#define NRI (Bn * HIN)              // 24256 interior rows total
#define ROWS 32                     // rows per countk strip
#define SPI ((HIN + ROWS - 1) / ROWS)   // 48 strips per image
#define RPT 24                      // rows per scan thread
#define THRV 0.6f

__device__ unsigned g_mask[(size_t)NRI * WPR];   // 4.7 MB candidate bitmask
__device__ int g_rowcnt[NRI];
__device__ int g_rowoff[NRI];

__device__ __forceinline__ float fmax3(float a, float b, float c) {
    return fmaxf(a, fmaxf(b, c));
}
// mid is candidate iff mid >= fmax(vl, v, vr, THR)  (conjunction fold)
__device__ __forceinline__ bool candf(float mid, float vl, float v, float vr) {
    return mid >= fmaxf(fmaxf(vl, v), fmaxf(vr, THRV));
}

__global__ __launch_bounds__(384, 3) void countk(const float* __restrict__ rep) {
    const int blk = blockIdx.x;
    const int b   = blk / SPI;
    const int s   = blk % SPI;
    const int y0  = 10 + s * ROWS;
    const int nrows = min(ROWS, (Hn - 10) - y0);
    const int tid  = threadIdx.x;
    const int lane = tid & 31;
    const int wid  = tid >> 5;
    const int g    = wid / 6;                 // row-half 0/1
    const int seg  = wid % 6;                 // 256-px column segment
    const int nr   = min(16, nrows - g * 16); // rows for this warp
    if (nr <= 0) return;
    const int ys   = y0 + g * 16;
    const int x0   = seg * 256 + lane * 8;
    const int t4   = x0 >> 2;                 // first float4 index

    const float* img = rep + (size_t)b * Hn * Wn;
    const float4* col = (const float4*)img;

    // halo column: lane 0 -> x0-1, lane 31 -> x0+8 (clamped; clamped bits border-masked)
    const bool isEdge = (lane == 0) | (lane == 31);
    const int hx = (lane == 0) ? max(x0 - 1, 0) : min(x0 + 8, Wn - 1);

    float4 rpA = col[(size_t)(ys - 1) * W4 + t4];
    float4 rpB = col[(size_t)(ys - 1) * W4 + t4 + 1];
    float4 rcA = col[(size_t)ys       * W4 + t4];
    float4 rcB = col[(size_t)ys       * W4 + t4 + 1];
    float hp = isEdge ? img[(size_t)(ys - 1) * Wn + hx] : 0.0f;
    float hc = isEdge ? img[(size_t)ys       * Wn + hx] : 0.0f;

    const int ridBase = b * HIN + (y0 - 10) + g * 16;
    const int gw = seg * 8 + (lane >> 2);         // global 32-bit word index 0..47
    // ushort store slot: even lanes store one 16-bit half each
    const bool leader = (lane & 1) == 0;
    const int uidx = gw * 2 + ((lane & 3) >> 1);  // ushort index within row
    unsigned short* gm16 = (unsigned short*)g_mask;

    #pragma unroll 4
    for (int i = 0; i < nr; ++i) {
        const int y = ys + i;
        const float4 rnA = col[(size_t)(y + 1) * W4 + t4];
        const float4 rnB = col[(size_t)(y + 1) * W4 + t4 + 1];
        const float hn = isEdge ? img[(size_t)(y + 1) * Wn + hx] : 0.0f;

        // vertical 3-max per pixel (includes center)
        const float v0 = fmax3(rpA.x, rcA.x, rnA.x);
        const float v1 = fmax3(rpA.y, rcA.y, rnA.y);
        const float v2 = fmax3(rpA.z, rcA.z, rnA.z);
        const float v3 = fmax3(rpA.w, rcA.w, rnA.w);
        const float v4 = fmax3(rpB.x, rcB.x, rnB.x);
        const float v5 = fmax3(rpB.y, rcB.y, rnB.y);
        const float v6 = fmax3(rpB.z, rcB.z, rnB.z);
        const float v7 = fmax3(rpB.w, rcB.w, rnB.w);
        const float hv = fmax3(hp, hc, hn);

        float left  = __shfl_up_sync(0xffffffffu, v7, 1);
        float right = __shfl_down_sync(0xffffffffu, v0, 1);
        if (lane == 0)  left  = hv;
        if (lane == 31) right = hv;

        // one compare per pixel (thr + 3x3-max folded into one fmax tree)
        const bool c0 = candf(rcA.x, left, v0, v1);
        const bool c1 = candf(rcA.y, v0,   v1, v2);
        const bool c2 = candf(rcA.z, v1,   v2, v3);
        const bool c3 = candf(rcA.w, v2,   v3, v4);
        const bool c4 = candf(rcB.x, v3,   v4, v5);
        const bool c5 = candf(rcB.y, v4,   v5, v6);
        const bool c6 = candf(rcB.z, v5,   v6, v7);
        const bool c7 = candf(rcB.w, v6,   v7, right);
        const unsigned nib =  (unsigned)c0        | ((unsigned)c1 << 1)
                           | ((unsigned)c2 << 2) | ((unsigned)c3 << 3)
                           | ((unsigned)c4 << 4) | ((unsigned)c5 << 5)
                           | ((unsigned)c6 << 6) | ((unsigned)c7 << 7);

        // pack lane pairs: one xor-shfl -> each pair holds a valid 16-bit half
        unsigned v = nib << (8 * (lane & 3));
        v |= __shfl_xor_sync(0xffffffffu, v, 1);
        if (gw == 0)       v &= ~0x3FFu;          // x < 10
        if (gw == WPR - 1) v &= 0x003FFFFFu;      // x >= 1526
        if (leader) {
            const unsigned short h =
                (unsigned short)((lane & 2) ? (v >> 16) : (v & 0xFFFFu));
            gm16[(size_t)(ridBase + i) * (WPR * 2) + uidx] = h;
        }

        rpA = rcA; rpB = rcB; rcA = rnA; rcB = rnB; hp = hc; hc = hn;
    }
}

__global__ __launch_bounds__(256) void rowcntk() {
    const int tid  = threadIdx.x;
    const int lane = tid & 31;
    const int r    = blockIdx.x * 8 + (tid >> 5);
    const unsigned* mrow = g_mask + (size_t)r * WPR;
    int c = __popc(mrow[lane]) + ((lane < WPR - 32) ? __popc(mrow[32 + lane]) : 0);
    #pragma unroll
    for (int o = 16; o > 0; o >>= 1)
        c += __shfl_down_sync(0xffffffffu, c, o);
    if (lane == 0) g_rowcnt[r] = c;
}

__global__ __launch_bounds__(1024) void scank() {
    const int tid  = threadIdx.x;
    const int lane = tid & 31;
    const int wid  = tid >> 5;
    int loc[RPT];
    int s = 0;
    #pragma unroll
    for (int i = 0; i < RPT; ++i) {
        const int idx = tid * RPT + i;
        loc[i] = s;
        s += (idx < NRI) ? g_rowcnt[idx] : 0;
    }
    int v = s;
    #pragma unroll
    for (int o = 1; o < 32; o <<= 1) {
        const int u = __shfl_up_sync(0xffffffffu, v, o);
        if (lane >= o) v += u;
    }
    __shared__ int ws[32];
    if (lane == 31) ws[wid] = v;
    __syncthreads();
    if (wid == 0) {
        int w = ws[lane];
        #pragma unroll
        for (int o = 1; o < 32; o <<= 1) {
            const int u = __shfl_up_sync(0xffffffffu, w, o);
            if (lane >= o) w += u;
        }
        ws[lane] = w;
    }
    __syncthreads();
    const int excl = (v - s) + (wid > 0 ? ws[wid - 1] : 0);
    #pragma unroll
    for (int i = 0; i < RPT; ++i) {
        const int idx = tid * RPT + i;
        if (idx < NRI) g_rowoff[idx] = excl + loc[i];
    }
}

__global__ __launch_bounds__(256) void emitk(float* __restrict__ out, int K) {
    __shared__ unsigned short sx[8][Wn];              // 24 KB: x-coords per row
    const int tid  = threadIdx.x;
    const int lane = tid & 31;
    const int wid  = tid >> 5;
    const int r    = blockIdx.x * 8 + wid;
    const int y    = 10 + r % HIN;
    const unsigned* mrow = g_mask + (size_t)r * WPR;
    const int off = g_rowoff[r];

    const unsigned wA = mrow[lane];
    const unsigned wB = (lane < WPR - 32) ? mrow[32 + lane] : 0u;
    const int pcA = __popc(wA);
    const int pcB = __popc(wB);

    int scA = pcA, scB = pcB;                         // inclusive warp scans
    #pragma unroll
    for (int o = 1; o < 32; o <<= 1) {
        const int uA = __shfl_up_sync(0xffffffffu, scA, o);
        const int uB = __shfl_up_sync(0xffffffffu, scB, o);
        if (lane >= o) { scA += uA; scB += uB; }
    }
    const int totalA = __shfl_sync(0xffffffffu, scA, 31);
    const int cnt    = totalA + __shfl_sync(0xffffffffu, scB, 31);

    // decode bits into smem x-list at ordered local offsets
    int j = scA - pcA;
    unsigned w = wA;
    int xb = lane * 32;
    while (w) {
        const int bit = __ffs(w) - 1;
        w &= w - 1;
        sx[wid][j++] = (unsigned short)(xb + bit);
    }
    j = totalA + scB - pcB;
    w = wB;
    xb = (32 + lane) * 32;
    while (w) {
        const int bit = __ffs(w) - 1;
        w &= w - 1;
        sx[wid][j++] = (unsigned short)(xb + bit);
    }
    __syncwarp();

    const float fy = (float)y;
    const int lim = min(cnt, K - off);                // defensive bound
    for (int i = lane; i < lim; i += 32) {
        out[off + i]     = fy;
        out[K + off + i] = (float)sx[wid][i];
    }
}

extern "C" void kernel_launch(void* const* d_in, const int* in_sizes, int n_in,
                              void* d_out, int out_size) {
    const float* rep = (const float*)d_in[0];
    float* out = (float*)d_out;
    const int K = out_size / 2;
    countk<<<Bn * SPI, 384>>>(rep);
    rowcntk<<<NRI / 8, 256>>>();
    scank<<<1, 1024>>>();
    emitk<<<NRI / 8, 256>>>(out, K);
}